// round 2
// baseline (speedup 1.0000x reference)
#include <cuda_runtime.h>
#include <math.h>

#define N_NODES 25000
#define N_EDGES 100000
#define H 64
#define K2 4224            // 4096 (P edge part) + 64 (h for roots) + 64 (Q for be3)
#define N_LAYERS 3

// ---------------- scratch (static device globals; no runtime allocation) ----
__device__ float g_h[N_NODES * H];
__device__ float g_hidden[N_NODES * H];
__device__ float g_ew2[N_EDGES * H];
__device__ float g_P[(size_t)N_NODES * K2];   // ~422 MB
__device__ float g_B[K2 * H];
__device__ float g_m[N_NODES * H];
__device__ int   g_deg[N_NODES];
__device__ int   g_off[N_NODES + 1];
__device__ int   g_cur[N_NODES];
__device__ int   g_csr[N_EDGES];

// ---------------- zero init ------------------------------------------------
__global__ void k_zero_misc() {
    int i = blockIdx.x * blockDim.x + threadIdx.x;
    int st = gridDim.x * blockDim.x;
    for (int idx = i; idx < N_NODES; idx += st) g_deg[idx] = 0;
    for (int idx = i; idx < N_NODES * H; idx += st) g_hidden[idx] = 0.f;
}

// ---------------- node MLP: h = (ReLU(ReLU(x W1^T+b1) W2^T+b2)) W3^T+b3 -----
__global__ void k_node_mlp(const float* __restrict__ x,
                           const float* __restrict__ W1, const float* __restrict__ b1,
                           const float* __restrict__ W2, const float* __restrict__ b2,
                           const float* __restrict__ W3, const float* __restrict__ b3) {
    __shared__ float W1T[32 * 64], W2T[64 * 64], W3T[64 * 64];
    __shared__ float b1s[64], b2s[64], b3s[64];
    __shared__ float xs[4][32], h1[4][64], h2[4][64];
    int tid = threadIdx.x;
    for (int idx = tid; idx < 32 * 64; idx += 256) { int o = idx / 32, j = idx % 32; W1T[j * 64 + o] = W1[idx]; }
    for (int idx = tid; idx < 64 * 64; idx += 256) { int o = idx / 64, j = idx % 64; W2T[j * 64 + o] = W2[idx]; W3T[j * 64 + o] = W3[idx]; }
    if (tid < 64) { b1s[tid] = b1[tid]; b2s[tid] = b2[tid]; b3s[tid] = b3[tid]; }
    __syncthreads();
    int nl = tid >> 6, o = tid & 63;
    for (int base = blockIdx.x * 4; base < N_NODES; base += gridDim.x * 4) {
        int node = base + nl;
        if (o < 32 && node < N_NODES) xs[nl][o] = x[node * 32 + o];
        __syncthreads();
        if (node < N_NODES) {
            float a = b1s[o];
            #pragma unroll
            for (int j = 0; j < 32; j++) a += xs[nl][j] * W1T[j * 64 + o];
            h1[nl][o] = fmaxf(a, 0.f);
        }
        __syncthreads();
        if (node < N_NODES) {
            float a = b2s[o];
            #pragma unroll
            for (int j = 0; j < 64; j++) a += h1[nl][j] * W2T[j * 64 + o];
            h2[nl][o] = fmaxf(a, 0.f);
        }
        __syncthreads();
        if (node < N_NODES) {
            float a = b3s[o];
            #pragma unroll
            for (int j = 0; j < 64; j++) a += h2[nl][j] * W3T[j * 64 + o];
            g_h[node * 64 + o] = a;                 // no ReLU on last layer
        }
        __syncthreads();
    }
}

// ---------------- edge MLP (layers 1 and 2 only; We3 is folded into GEMM) ---
__global__ void k_edge_mlp(const float* __restrict__ ea,
                           const float* __restrict__ W1, const float* __restrict__ b1,
                           const float* __restrict__ W2, const float* __restrict__ b2) {
    __shared__ float W1T[16 * 64], W2T[64 * 64];
    __shared__ float b1s[64], b2s[64];
    __shared__ float es[4][16], h1[4][64];
    int tid = threadIdx.x;
    for (int idx = tid; idx < 16 * 64; idx += 256) { int o = idx >> 4, j = idx & 15; W1T[j * 64 + o] = W1[idx]; }
    for (int idx = tid; idx < 64 * 64; idx += 256) { int o = idx >> 6, j = idx & 63; W2T[j * 64 + o] = W2[idx]; }
    if (tid < 64) { b1s[tid] = b1[tid]; b2s[tid] = b2[tid]; }
    __syncthreads();
    int nl = tid >> 6, o = tid & 63;
    for (int base = blockIdx.x * 4; base < N_EDGES; base += gridDim.x * 4) {
        int e = base + nl;
        if (o < 16 && e < N_EDGES) es[nl][o] = ea[e * 16 + o];
        __syncthreads();
        if (e < N_EDGES) {
            float a = b1s[o];
            #pragma unroll
            for (int j = 0; j < 16; j++) a += es[nl][j] * W1T[j * 64 + o];
            h1[nl][o] = fmaxf(a, 0.f);
        }
        __syncthreads();
        if (e < N_EDGES) {
            float a = b2s[o];
            #pragma unroll
            for (int j = 0; j < 64; j++) a += h1[nl][j] * W2T[j * 64 + o];
            g_ew2[e * 64 + o] = fmaxf(a, 0.f);      // ReLU after layer 2 (per reference)
        }
        __syncthreads();
    }
}

// ---------------- CSR build (dst-grouped) -----------------------------------
__global__ void k_hist(const int* __restrict__ ei) {
    int i = blockIdx.x * blockDim.x + threadIdx.x, st = gridDim.x * blockDim.x;
    for (int e = i; e < N_EDGES; e += st) atomicAdd(&g_deg[ei[N_EDGES + e]], 1);
}

__global__ void k_scan() {                       // single block, 1024 threads
    __shared__ int part[1024];
    int t = threadIdx.x;
    const int CH = (N_NODES + 1023) / 1024;      // 25
    int b0 = t * CH, b1 = min(b0 + CH, N_NODES);
    int s = 0;
    for (int i = b0; i < b1; i++) s += g_deg[i];
    part[t] = s;
    __syncthreads();
    for (int d = 1; d < 1024; d <<= 1) {
        int v = (t >= d) ? part[t - d] : 0;
        __syncthreads();
        part[t] += v;
        __syncthreads();
    }
    int run = (t == 0) ? 0 : part[t - 1];
    for (int i = b0; i < b1; i++) { g_off[i] = run; g_cur[i] = run; run += g_deg[i]; }
    if (t == 1023) g_off[N_NODES] = part[1023];
}

__global__ void k_fill(const int* __restrict__ ei) {
    int i = blockIdx.x * blockDim.x + threadIdx.x, st = gridDim.x * blockDim.x;
    for (int e = i; e < N_EDGES; e += st) {
        int d = ei[N_EDGES + e];
        int p = atomicAdd(&g_cur[d], 1);          // arbitrary order; consumer sorts
        g_csr[p] = e;
    }
}

// ---------------- build B[K2][64] for layer l --------------------------------
// rows [0,4096):   B[i*64+k][o] = We3[(i*64+o)*64 + k]
// rows [4096,4160): B[4096+i][o] = roots[l][i][o]
// rows [4160,4224): B[4160+i][o] = be3[i*64+o]
__global__ void k_buildB(const float* __restrict__ We3, const float* __restrict__ be3,
                         const float* __restrict__ roots, int l) {
    int i0 = blockIdx.x * blockDim.x + threadIdx.x, st = gridDim.x * blockDim.x;
    for (int idx = i0; idx < K2 * 64; idx += st) {
        int r = idx >> 6, o = idx & 63;
        float v;
        if (r < 4096) { int i = r >> 6, k = r & 63; v = We3[((i << 6) + o) * 64 + k]; }
        else if (r < 4160) { int i = r - 4096; v = roots[(l * 64 + i) * 64 + o]; }
        else { int i = r - 4160; v = be3[((r - 4160) << 6) + o]; (void)i; }
        g_B[idx] = v;
    }
}

// ---------------- build P rows (one warp per dst node) ----------------------
// Edges consumed in ascending edge-id order (warp min-extraction) so fp32 sums
// are bitwise deterministic despite the atomic CSR fill.
__global__ void k_buildP(const int* __restrict__ ei) {
    __shared__ float Pacc[2][64 * 64];
    __shared__ float Qacc[2][64];
    int warp = threadIdx.x >> 5, lane = threadIdx.x & 31;
    int d = blockIdx.x * 2 + warp;
    if (d >= N_NODES) return;
    float* P = Pacc[warp];
    for (int idx = lane; idx < 4096; idx += 32) P[idx] = 0.f;
    Qacc[warp][lane] = 0.f; Qacc[warp][lane + 32] = 0.f;
    __syncwarp();

    int off0 = g_off[d];
    int deg = g_off[d + 1] - off0;
    int prev = -1;
    for (int j = 0; j < deg; j++) {
        // find smallest edge id > prev in this node's list
        int mn = 0x7fffffff;
        for (int b = lane; b < deg; b += 32) {
            int v = g_csr[off0 + b];
            if (v > prev && v < mn) mn = v;
        }
        #pragma unroll
        for (int w = 16; w > 0; w >>= 1) {
            int o = __shfl_xor_sync(0xffffffffu, mn, w);
            mn = min(mn, o);
        }
        int e = mn; prev = mn;
        int s = ei[e];                                  // src node (broadcast)
        float ew0 = g_ew2[e * 64 + lane];
        float ew1 = g_ew2[e * 64 + 32 + lane];
        #pragma unroll 4
        for (int i = 0; i < 64; i++) {
            float hv = g_h[s * 64 + i];                 // broadcast load
            P[i * 64 + lane]      += hv * ew0;
            P[i * 64 + 32 + lane] += hv * ew1;
            if (lane == 0) Qacc[warp][i] += hv;
        }
    }
    __syncwarp();
    float* out = &g_P[(size_t)d * K2];
    for (int idx = lane; idx < 4096; idx += 32) out[idx] = P[idx];
    out[4096 + lane]      = g_h[d * 64 + lane];
    out[4096 + 32 + lane] = g_h[d * 64 + 32 + lane];
    out[4160 + lane]      = Qacc[warp][lane];
    out[4160 + 32 + lane] = Qacc[warp][lane + 32];
}

// ---------------- conv GEMM: m = P[N,K2] @ B[K2,64] + conv_bias[l] ----------
__global__ void k_gemm(const float* __restrict__ cbias, int l) {
    __shared__ __align__(16) float As[64][32];
    __shared__ __align__(16) float Bs[32][64];
    int tid = threadIdx.x;
    int m0blk = blockIdx.x * 64;
    int tx = tid & 15, ty = tid >> 4;
    int o0 = tx * 4, m0 = ty * 4;
    float acc[4][4] = {};

    for (int k0 = 0; k0 < K2; k0 += 32) {
        #pragma unroll
        for (int q = 0; q < 2; q++) {               // A tile: 64x32 = 512 float4
            int f = tid * 2 + q;
            int row = f >> 3, c4 = f & 7;
            float4 v = make_float4(0.f, 0.f, 0.f, 0.f);
            if (m0blk + row < N_NODES)
                v = *(const float4*)&g_P[(size_t)(m0blk + row) * K2 + k0 + c4 * 4];
            *(float4*)&As[row][c4 * 4] = v;
        }
        #pragma unroll
        for (int q = 0; q < 2; q++) {               // B tile: 32x64 = 512 float4
            int f = tid * 2 + q;
            int row = f >> 4, c4 = f & 15;
            *(float4*)&Bs[row][c4 * 4] = *(const float4*)&g_B[(k0 + row) * 64 + c4 * 4];
        }
        __syncthreads();
        #pragma unroll
        for (int k = 0; k < 32; k++) {
            float4 b = *(float4*)&Bs[k][o0];
            #pragma unroll
            for (int mm = 0; mm < 4; mm++) {
                float a = As[m0 + mm][k];
                acc[mm][0] += a * b.x; acc[mm][1] += a * b.y;
                acc[mm][2] += a * b.z; acc[mm][3] += a * b.w;
            }
        }
        __syncthreads();
    }
    #pragma unroll
    for (int mm = 0; mm < 4; mm++) {
        int m = m0blk + m0 + mm;
        if (m < N_NODES) {
            float* dst = &g_m[m * 64 + o0];
            dst[0] = acc[mm][0] + cbias[l * 64 + o0 + 0];
            dst[1] = acc[mm][1] + cbias[l * 64 + o0 + 1];
            dst[2] = acc[mm][2] + cbias[l * 64 + o0 + 2];
            dst[3] = acc[mm][3] + cbias[l * 64 + o0 + 3];
        }
    }
}

// ---------------- GRU step ---------------------------------------------------
#define GRU_SMEM ((24576 + 192 * 2 + 64 * 2 + 192 * 2) * 4)
__global__ void k_gru(const float* __restrict__ Wih, const float* __restrict__ Whh,
                      const float* __restrict__ bih, const float* __restrict__ bhh,
                      float* __restrict__ dout, int last) {
    extern __shared__ float sm[];
    float* WihT = sm;                // [i*192 + j]
    float* WhhT = sm + 12288;
    float* bihs = sm + 24576;
    float* bhhs = bihs + 192;
    float* ms   = bhhs + 192;
    float* hs   = ms + 64;
    float* gi   = hs + 64;
    float* gh   = gi + 192;
    int t = threadIdx.x;             // 192 threads
    for (int idx = t; idx < 192 * 64; idx += 192) {
        int j = idx / 64, i = idx % 64;
        WihT[i * 192 + j] = Wih[idx];
        WhhT[i * 192 + j] = Whh[idx];
    }
    bihs[t] = bih[t]; bhhs[t] = bhh[t];
    __syncthreads();
    for (int node = blockIdx.x; node < N_NODES; node += gridDim.x) {
        if (t < 64) { ms[t] = g_m[node * 64 + t]; hs[t] = g_hidden[node * 64 + t]; }
        __syncthreads();
        float a = bihs[t], b = bhhs[t];
        #pragma unroll 8
        for (int i = 0; i < 64; i++) {
            a += ms[i] * WihT[i * 192 + t];
            b += hs[i] * WhhT[i * 192 + t];
        }
        gi[t] = a; gh[t] = b;
        __syncthreads();
        if (t < 64) {
            float r = 1.f / (1.f + expf(-(gi[t] + gh[t])));
            float z = 1.f / (1.f + expf(-(gi[64 + t] + gh[64 + t])));
            float n = tanhf(gi[128 + t] + r * gh[128 + t]);
            float nh = (1.f - z) * n + z * hs[t];
            g_hidden[node * 64 + t] = nh;
            g_h[node * 64 + t] = nh;
            if (last) dout[node * 64 + t] = nh;
        }
        __syncthreads();
    }
}

// ---------------- launcher ----------------------------------------------------
extern "C" void kernel_launch(void* const* d_in, const int* in_sizes, int n_in,
                              void* d_out, int out_size) {
    const float* x     = (const float*)d_in[0];
    const float* ea    = (const float*)d_in[1];
    const float* Wn1   = (const float*)d_in[2];
    const float* bn1   = (const float*)d_in[3];
    const float* Wn2   = (const float*)d_in[4];
    const float* bn2   = (const float*)d_in[5];
    const float* Wn3   = (const float*)d_in[6];
    const float* bn3   = (const float*)d_in[7];
    const float* We1   = (const float*)d_in[8];
    const float* be1   = (const float*)d_in[9];
    const float* We2   = (const float*)d_in[10];
    const float* be2   = (const float*)d_in[11];
    const float* We3   = (const float*)d_in[12];
    const float* be3   = (const float*)d_in[13];
    const float* roots = (const float*)d_in[14];
    const float* cbias = (const float*)d_in[15];
    const float* gWih  = (const float*)d_in[16];
    const float* gWhh  = (const float*)d_in[17];
    const float* gbih  = (const float*)d_in[18];
    const float* gbhh  = (const float*)d_in[19];
    const int*   ei    = (const int*)d_in[20];
    float* dout = (float*)d_out;

    cudaFuncSetAttribute(k_gru, cudaFuncAttributeMaxDynamicSharedMemorySize, GRU_SMEM);

    k_zero_misc<<<128, 256>>>();
    k_node_mlp<<<296, 256>>>(x, Wn1, bn1, Wn2, bn2, Wn3, bn3);
    k_edge_mlp<<<296, 256>>>(ea, We1, be1, We2, be2);
    k_hist<<<200, 256>>>(ei);
    k_scan<<<1, 1024>>>();
    k_fill<<<200, 256>>>(ei);

    for (int l = 0; l < N_LAYERS; l++) {
        k_buildB<<<264, 256>>>(We3, be3, roots, l);
        k_buildP<<<(N_NODES + 1) / 2, 64>>>(ei);
        k_gemm<<<(N_NODES + 63) / 64, 256>>>(cbias, l);
        k_gru<<<296, 192, GRU_SMEM>>>(gWih, gWhh, gbih, gbhh, dout, l == N_LAYERS - 1);
    }
}

// round 4
// speedup vs baseline: 1.2470x; 1.2470x over previous
#include <cuda_runtime.h>
#include <cuda_bf16.h>
#include <cstdint>
#include <math.h>

#define N_NODES 25000
#define M_PAD   25088            // 196 * 128
#define N_EDGES 100000
#define H 64
#define K2 4224                  // 4096 (P edge part) + 64 (h for roots) + 64 (Q for be3)
#define NKB 66                   // K2 / 64
#define N_LAYERS 3

// ---------------- scratch (static device globals) ---------------------------
__device__ float g_h[N_NODES * H];
__device__ float g_hidden[N_NODES * H];
__device__ float g_ew2[N_EDGES * H];
__device__ __align__(128) __nv_bfloat16 g_Phi[(size_t)M_PAD * K2];   // ~212 MB
__device__ __align__(128) __nv_bfloat16 g_Plo[(size_t)M_PAD * K2];   // ~212 MB
__device__ __align__(128) __nv_bfloat16 g_Bhi[H * K2];               // Bt[n][k]
__device__ __align__(128) __nv_bfloat16 g_Blo[H * K2];
__device__ float g_m[N_NODES * H];
__device__ int   g_deg[N_NODES];
__device__ int   g_off[N_NODES + 1];
__device__ int   g_cur[N_NODES];
__device__ int   g_csr[N_EDGES];

// ---------------- helpers ------------------------------------------------
__device__ __forceinline__ uint32_t smem_u32(const void* p) {
    uint32_t a;
    asm("{ .reg .u64 t; cvta.to.shared.u64 t, %1; cvt.u32.u64 %0, t; }" : "=r"(a) : "l"(p));
    return a;
}

__device__ __forceinline__ void mma16816(float* c, const uint32_t* a, uint32_t b0, uint32_t b1) {
    asm volatile("mma.sync.aligned.m16n8k16.row.col.f32.bf16.bf16.f32 "
        "{%0,%1,%2,%3}, {%4,%5,%6,%7}, {%8,%9}, {%0,%1,%2,%3};"
        : "+f"(c[0]), "+f"(c[1]), "+f"(c[2]), "+f"(c[3])
        : "r"(a[0]), "r"(a[1]), "r"(a[2]), "r"(a[3]), "r"(b0), "r"(b1));
}

// ---------------- zero init --------------------------------------------------
__global__ void k_zero_misc() {
    int i = blockIdx.x * blockDim.x + threadIdx.x;
    int st = gridDim.x * blockDim.x;
    for (int idx = i; idx < N_NODES; idx += st) g_deg[idx] = 0;
    for (int idx = i; idx < N_NODES * H; idx += st) g_hidden[idx] = 0.f;
    const size_t padN = (size_t)(M_PAD - N_NODES) * K2;
    __nv_bfloat16 z = __float2bfloat16(0.f);
    for (size_t idx = i; idx < padN; idx += st) {
        g_Phi[(size_t)N_NODES * K2 + idx] = z;
        g_Plo[(size_t)N_NODES * K2 + idx] = z;
    }
}

// ---------------- node MLP ---------------------------------------------------
__global__ void k_node_mlp(const float* __restrict__ x,
                           const float* __restrict__ W1, const float* __restrict__ b1,
                           const float* __restrict__ W2, const float* __restrict__ b2,
                           const float* __restrict__ W3, const float* __restrict__ b3) {
    __shared__ float W1T[32 * 64], W2T[64 * 64], W3T[64 * 64];
    __shared__ float b1s[64], b2s[64], b3s[64];
    __shared__ float xs[4][32], h1[4][64], h2[4][64];
    int tid = threadIdx.x;
    for (int idx = tid; idx < 32 * 64; idx += 256) { int o = idx / 32, j = idx % 32; W1T[j * 64 + o] = W1[idx]; }
    for (int idx = tid; idx < 64 * 64; idx += 256) { int o = idx / 64, j = idx % 64; W2T[j * 64 + o] = W2[idx]; W3T[j * 64 + o] = W3[idx]; }
    if (tid < 64) { b1s[tid] = b1[tid]; b2s[tid] = b2[tid]; b3s[tid] = b3[tid]; }
    __syncthreads();
    int nl = tid >> 6, o = tid & 63;
    for (int base = blockIdx.x * 4; base < N_NODES; base += gridDim.x * 4) {
        int node = base + nl;
        if (o < 32 && node < N_NODES) xs[nl][o] = x[node * 32 + o];
        __syncthreads();
        if (node < N_NODES) {
            float a = b1s[o];
            #pragma unroll
            for (int j = 0; j < 32; j++) a += xs[nl][j] * W1T[j * 64 + o];
            h1[nl][o] = fmaxf(a, 0.f);
        }
        __syncthreads();
        if (node < N_NODES) {
            float a = b2s[o];
            #pragma unroll
            for (int j = 0; j < 64; j++) a += h1[nl][j] * W2T[j * 64 + o];
            h2[nl][o] = fmaxf(a, 0.f);
        }
        __syncthreads();
        if (node < N_NODES) {
            float a = b3s[o];
            #pragma unroll
            for (int j = 0; j < 64; j++) a += h2[nl][j] * W3T[j * 64 + o];
            g_h[node * 64 + o] = a;
        }
        __syncthreads();
    }
}

// ---------------- edge MLP (layers 1,2) --------------------------------------
__global__ void k_edge_mlp(const float* __restrict__ ea,
                           const float* __restrict__ W1, const float* __restrict__ b1,
                           const float* __restrict__ W2, const float* __restrict__ b2) {
    __shared__ float W1T[16 * 64], W2T[64 * 64];
    __shared__ float b1s[64], b2s[64];
    __shared__ float es[4][16], h1[4][64];
    int tid = threadIdx.x;
    for (int idx = tid; idx < 16 * 64; idx += 256) { int o = idx >> 4, j = idx & 15; W1T[j * 64 + o] = W1[idx]; }
    for (int idx = tid; idx < 64 * 64; idx += 256) { int o = idx >> 6, j = idx & 63; W2T[j * 64 + o] = W2[idx]; }
    if (tid < 64) { b1s[tid] = b1[tid]; b2s[tid] = b2[tid]; }
    __syncthreads();
    int nl = tid >> 6, o = tid & 63;
    for (int base = blockIdx.x * 4; base < N_EDGES; base += gridDim.x * 4) {
        int e = base + nl;
        if (o < 16 && e < N_EDGES) es[nl][o] = ea[e * 16 + o];
        __syncthreads();
        if (e < N_EDGES) {
            float a = b1s[o];
            #pragma unroll
            for (int j = 0; j < 16; j++) a += es[nl][j] * W1T[j * 64 + o];
            h1[nl][o] = fmaxf(a, 0.f);
        }
        __syncthreads();
        if (e < N_EDGES) {
            float a = b2s[o];
            #pragma unroll
            for (int j = 0; j < 64; j++) a += h1[nl][j] * W2T[j * 64 + o];
            g_ew2[e * 64 + o] = fmaxf(a, 0.f);
        }
        __syncthreads();
    }
}

// ---------------- CSR build --------------------------------------------------
__global__ void k_hist(const int* __restrict__ ei) {
    int i = blockIdx.x * blockDim.x + threadIdx.x, st = gridDim.x * blockDim.x;
    for (int e = i; e < N_EDGES; e += st) atomicAdd(&g_deg[ei[N_EDGES + e]], 1);
}

__global__ void k_scan() {
    __shared__ int part[1024];
    int t = threadIdx.x;
    const int CH = (N_NODES + 1023) / 1024;
    int b0 = t * CH, b1 = min(b0 + CH, N_NODES);
    int s = 0;
    for (int i = b0; i < b1; i++) s += g_deg[i];
    part[t] = s;
    __syncthreads();
    for (int d = 1; d < 1024; d <<= 1) {
        int v = (t >= d) ? part[t - d] : 0;
        __syncthreads();
        part[t] += v;
        __syncthreads();
    }
    int run = (t == 0) ? 0 : part[t - 1];
    for (int i = b0; i < b1; i++) { g_off[i] = run; g_cur[i] = run; run += g_deg[i]; }
    if (t == 1023) g_off[N_NODES] = part[1023];
}

__global__ void k_fill(const int* __restrict__ ei) {
    int i = blockIdx.x * blockDim.x + threadIdx.x, st = gridDim.x * blockDim.x;
    for (int e = i; e < N_EDGES; e += st) {
        int d = ei[N_EDGES + e];
        int p = atomicAdd(&g_cur[d], 1);
        g_csr[p] = e;
    }
}

// ---------------- build Bt[n][k] (bf16 hi/lo) for layer l --------------------
__global__ void k_buildB(const float* __restrict__ We3, const float* __restrict__ be3,
                         const float* __restrict__ roots, int l) {
    int i0 = blockIdx.x * blockDim.x + threadIdx.x, st = gridDim.x * blockDim.x;
    for (int idx = i0; idx < H * K2; idx += st) {
        int n = idx / K2, kg = idx % K2;
        float v;
        if (kg < 4096)      { int i = kg >> 6, k = kg & 63; v = We3[((i << 6) + n) * 64 + k]; }
        else if (kg < 4160) { v = roots[(l * 64 + (kg - 4096)) * 64 + n]; }
        else                { v = be3[((kg - 4160) << 6) + n]; }
        __nv_bfloat16 hi = __float2bfloat16(v);
        g_Bhi[idx] = hi;
        g_Blo[idx] = __float2bfloat16(v - __bfloat162float(hi));
    }
}

// ---------------- build P rows (bf16 hi/lo; one warp per dst node) -----------
__global__ void k_buildP(const int* __restrict__ ei) {
    __shared__ float Pacc[2][64 * 64];
    __shared__ float Qacc[2][64];
    int warp = threadIdx.x >> 5, lane = threadIdx.x & 31;
    int d = blockIdx.x * 2 + warp;
    if (d >= N_NODES) return;
    float* P = Pacc[warp];
    for (int idx = lane; idx < 4096; idx += 32) P[idx] = 0.f;
    Qacc[warp][lane] = 0.f; Qacc[warp][lane + 32] = 0.f;
    __syncwarp();

    int off0 = g_off[d];
    int deg = g_off[d + 1] - off0;
    int prev = -1;
    for (int j = 0; j < deg; j++) {
        int mn = 0x7fffffff;
        for (int b = lane; b < deg; b += 32) {
            int v = g_csr[off0 + b];
            if (v > prev && v < mn) mn = v;
        }
        #pragma unroll
        for (int w = 16; w > 0; w >>= 1) {
            int o = __shfl_xor_sync(0xffffffffu, mn, w);
            mn = min(mn, o);
        }
        int e = mn; prev = mn;
        int s = ei[e];
        float ew0 = g_ew2[e * 64 + lane];
        float ew1 = g_ew2[e * 64 + 32 + lane];
        #pragma unroll 4
        for (int i = 0; i < 64; i++) {
            float hv = g_h[s * 64 + i];
            P[i * 64 + lane]      += hv * ew0;
            P[i * 64 + 32 + lane] += hv * ew1;
            if (lane == 0) Qacc[warp][i] += hv;
        }
    }
    __syncwarp();
    size_t rb = (size_t)d * K2;
    for (int idx = lane; idx < 4096; idx += 32) {
        float v = P[idx];
        __nv_bfloat16 hi = __float2bfloat16(v);
        g_Phi[rb + idx] = hi;
        g_Plo[rb + idx] = __float2bfloat16(v - __bfloat162float(hi));
    }
    #pragma unroll
    for (int q = 0; q < 2; q++) {
        float hv = g_h[d * 64 + q * 32 + lane];
        __nv_bfloat16 hhi = __float2bfloat16(hv);
        g_Phi[rb + 4096 + q * 32 + lane] = hhi;
        g_Plo[rb + 4096 + q * 32 + lane] = __float2bfloat16(hv - __bfloat162float(hhi));
        float qv = Qacc[warp][q * 32 + lane];
        __nv_bfloat16 qhi = __float2bfloat16(qv);
        g_Phi[rb + 4160 + q * 32 + lane] = qhi;
        g_Plo[rb + 4160 + q * 32 + lane] = __float2bfloat16(qv - __bfloat162float(qhi));
    }
}

// ---------------- mma.sync GEMM: m = P @ Bt^T + cbias -------------------------
// Stage layout (bf16 elems, padded rows of 72): Ahi[128][72] @0, Alo @9216,
// Bhi[64][72] @18432, Blo @23040; stage = 27648 elems = 55296 B. 2 stages.
#define AHI_OFF 0
#define ALO_OFF 9216
#define BHI_OFF 18432
#define BLO_OFF 23040
#define STAGE_ELEMS 27648
#define GEMM_SMEM (2 * STAGE_ELEMS * 2)

__device__ __forceinline__ void load_stage(__nv_bfloat16* st, int m0, int kblk, int tid) {
    #pragma unroll
    for (int q = 0; q < 24; q++) {
        int c = q * 128 + tid;                    // 0..3071 chunks of 16B
        const __nv_bfloat16* src;
        __nv_bfloat16* dst;
        if (c < 2048) {                           // A planes: 128 rows x 8 chunks
            int half = c >> 10, cc = c & 1023;
            int row = cc >> 3, c8 = cc & 7;
            const __nv_bfloat16* g = half ? g_Plo : g_Phi;
            src = g + (size_t)(m0 + row) * K2 + kblk * 64 + c8 * 8;
            dst = st + (half ? ALO_OFF : AHI_OFF) + row * 72 + c8 * 8;
        } else {                                  // B planes: 64 rows x 8 chunks
            int c2 = c - 2048;
            int half = c2 >> 9, cc = c2 & 511;
            int row = cc >> 3, c8 = cc & 7;
            const __nv_bfloat16* g = half ? g_Blo : g_Bhi;
            src = g + (size_t)row * K2 + kblk * 64 + c8 * 8;
            dst = st + (half ? BLO_OFF : BHI_OFF) + row * 72 + c8 * 8;
        }
        uint32_t d32 = smem_u32(dst);
        asm volatile("cp.async.cg.shared.global [%0], [%1], 16;" :: "r"(d32), "l"(src));
    }
    asm volatile("cp.async.commit_group;" ::: "memory");
}

__global__ void __launch_bounds__(128, 2) k_gemm_mma(const float* __restrict__ cbias, int l) {
    extern __shared__ __align__(16) __nv_bfloat16 sm[];
    const int tid = threadIdx.x, w = tid >> 5, lane = tid & 31;
    const int m0 = blockIdx.x * 128;
    const int lq = lane >> 2;          // 0..7
    const int lr = lane & 3;           // 0..3

    float acc[2][8][4];
    #pragma unroll
    for (int ma = 0; ma < 2; ma++)
        #pragma unroll
        for (int na = 0; na < 8; na++)
            #pragma unroll
            for (int v = 0; v < 4; v++) acc[ma][na][v] = 0.f;

    load_stage(sm, m0, 0, tid);
    load_stage(sm + STAGE_ELEMS, m0, 1, tid);

    for (int blk = 0; blk < NKB; blk++) {
        if (blk == NKB - 1) asm volatile("cp.async.wait_group 0;" ::: "memory");
        else                asm volatile("cp.async.wait_group 1;" ::: "memory");
        __syncthreads();
        __nv_bfloat16* st = sm + (blk & 1) * STAGE_ELEMS;
        const __nv_bfloat16* Ahi = st + AHI_OFF;
        const __nv_bfloat16* Alo = st + ALO_OFF;
        const __nv_bfloat16* Bhi = st + BHI_OFF;
        const __nv_bfloat16* Blo = st + BLO_OFF;

        #pragma unroll
        for (int s = 0; s < 4; s++) {
            int k0 = s * 16;
            uint32_t ahi[2][4], alo[2][4];
            #pragma unroll
            for (int ma = 0; ma < 2; ma++) {
                int r = w * 32 + ma * 16 + lq;
                ahi[ma][0] = *(const uint32_t*)&Ahi[r * 72 + k0 + lr * 2];
                ahi[ma][1] = *(const uint32_t*)&Ahi[(r + 8) * 72 + k0 + lr * 2];
                ahi[ma][2] = *(const uint32_t*)&Ahi[r * 72 + k0 + 8 + lr * 2];
                ahi[ma][3] = *(const uint32_t*)&Ahi[(r + 8) * 72 + k0 + 8 + lr * 2];
                alo[ma][0] = *(const uint32_t*)&Alo[r * 72 + k0 + lr * 2];
                alo[ma][1] = *(const uint32_t*)&Alo[(r + 8) * 72 + k0 + lr * 2];
                alo[ma][2] = *(const uint32_t*)&Alo[r * 72 + k0 + 8 + lr * 2];
                alo[ma][3] = *(const uint32_t*)&Alo[(r + 8) * 72 + k0 + 8 + lr * 2];
            }
            #pragma unroll
            for (int na = 0; na < 8; na++) {
                int rn = na * 8 + lq;
                uint32_t bh0 = *(const uint32_t*)&Bhi[rn * 72 + k0 + lr * 2];
                uint32_t bh1 = *(const uint32_t*)&Bhi[rn * 72 + k0 + 8 + lr * 2];
                uint32_t bl0 = *(const uint32_t*)&Blo[rn * 72 + k0 + lr * 2];
                uint32_t bl1 = *(const uint32_t*)&Blo[rn * 72 + k0 + 8 + lr * 2];
                #pragma unroll
                for (int ma = 0; ma < 2; ma++) {
                    mma16816(acc[ma][na], ahi[ma], bh0, bh1);
                    mma16816(acc[ma][na], ahi[ma], bl0, bl1);
                    mma16816(acc[ma][na], alo[ma], bh0, bh1);
                }
            }
        }
        __syncthreads();
        if (blk + 2 < NKB) load_stage(st, m0, blk + 2, tid);
    }

    // epilogue: acc rows m0 + w*32 + ma*16 + lq (+8), cols na*8 + lr*2 (+1)
    #pragma unroll
    for (int ma = 0; ma < 2; ma++) {
        int r0 = m0 + w * 32 + ma * 16 + lq;
        #pragma unroll
        for (int na = 0; na < 8; na++) {
            int c0 = na * 8 + lr * 2;
            float bx = cbias[l * 64 + c0], by = cbias[l * 64 + c0 + 1];
            if (r0 < N_NODES) {
                g_m[r0 * 64 + c0]     = acc[ma][na][0] + bx;
                g_m[r0 * 64 + c0 + 1] = acc[ma][na][1] + by;
            }
            if (r0 + 8 < N_NODES) {
                g_m[(r0 + 8) * 64 + c0]     = acc[ma][na][2] + bx;
                g_m[(r0 + 8) * 64 + c0 + 1] = acc[ma][na][3] + by;
            }
        }
    }
}

// ---------------- GRU step ---------------------------------------------------
#define GRU_SMEM ((24576 + 192 * 2 + 64 * 2 + 192 * 2) * 4)
__global__ void k_gru(const float* __restrict__ Wih, const float* __restrict__ Whh,
                      const float* __restrict__ bih, const float* __restrict__ bhh,
                      float* __restrict__ dout, int last) {
    extern __shared__ float smf[];
    float* WihT = smf;
    float* WhhT = smf + 12288;
    float* bihs = smf + 24576;
    float* bhhs = bihs + 192;
    float* ms   = bhhs + 192;
    float* hs   = ms + 64;
    float* gi   = hs + 64;
    float* gh   = gi + 192;
    int t = threadIdx.x;
    for (int idx = t; idx < 192 * 64; idx += 192) {
        int j = idx / 64, i = idx % 64;
        WihT[i * 192 + j] = Wih[idx];
        WhhT[i * 192 + j] = Whh[idx];
    }
    bihs[t] = bih[t]; bhhs[t] = bhh[t];
    __syncthreads();
    for (int node = blockIdx.x; node < N_NODES; node += gridDim.x) {
        if (t < 64) { ms[t] = g_m[node * 64 + t]; hs[t] = g_hidden[node * 64 + t]; }
        __syncthreads();
        float a = bihs[t], b = bhhs[t];
        #pragma unroll 8
        for (int i = 0; i < 64; i++) {
            a += ms[i] * WihT[i * 192 + t];
            b += hs[i] * WhhT[i * 192 + t];
        }
        gi[t] = a; gh[t] = b;
        __syncthreads();
        if (t < 64) {
            float r = 1.f / (1.f + expf(-(gi[t] + gh[t])));
            float z = 1.f / (1.f + expf(-(gi[64 + t] + gh[64 + t])));
            float n = tanhf(gi[128 + t] + r * gh[128 + t]);
            float nh = (1.f - z) * n + z * hs[t];
            g_hidden[node * 64 + t] = nh;
            g_h[node * 64 + t] = nh;
            if (last) dout[node * 64 + t] = nh;
        }
        __syncthreads();
    }
}

// ---------------- launcher ----------------------------------------------------
extern "C" void kernel_launch(void* const* d_in, const int* in_sizes, int n_in,
                              void* d_out, int out_size) {
    const float* x     = (const float*)d_in[0];
    const float* ea    = (const float*)d_in[1];
    const float* Wn1   = (const float*)d_in[2];
    const float* bn1   = (const float*)d_in[3];
    const float* Wn2   = (const float*)d_in[4];
    const float* bn2   = (const float*)d_in[5];
    const float* Wn3   = (const float*)d_in[6];
    const float* bn3   = (const float*)d_in[7];
    const float* We1   = (const float*)d_in[8];
    const float* be1   = (const float*)d_in[9];
    const float* We2   = (const float*)d_in[10];
    const float* be2   = (const float*)d_in[11];
    const float* We3   = (const float*)d_in[12];
    const float* be3   = (const float*)d_in[13];
    const float* roots = (const float*)d_in[14];
    const float* cbias = (const float*)d_in[15];
    const float* gWih  = (const float*)d_in[16];
    const float* gWhh  = (const float*)d_in[17];
    const float* gbih  = (const float*)d_in[18];
    const float* gbhh  = (const float*)d_in[19];
    const int*   ei    = (const int*)d_in[20];
    float* dout = (float*)d_out;

    cudaFuncSetAttribute(k_gru, cudaFuncAttributeMaxDynamicSharedMemorySize, GRU_SMEM);
    cudaFuncSetAttribute(k_gemm_mma, cudaFuncAttributeMaxDynamicSharedMemorySize, GEMM_SMEM);

    k_zero_misc<<<400, 256>>>();
    k_node_mlp<<<296, 256>>>(x, Wn1, bn1, Wn2, bn2, Wn3, bn3);
    k_edge_mlp<<<296, 256>>>(ea, We1, be1, We2, be2);
    k_hist<<<200, 256>>>(ei);
    k_scan<<<1, 1024>>>();
    k_fill<<<200, 256>>>(ei);

    for (int l = 0; l < N_LAYERS; l++) {
        k_buildB<<<264, 256>>>(We3, be3, roots, l);
        k_buildP<<<(N_NODES + 1) / 2, 64>>>(ei);
        k_gemm_mma<<<M_PAD / 128, 128, GEMM_SMEM>>>(cbias, l);
        k_gru<<<296, 192, GRU_SMEM>>>(gWih, gWhh, gbih, gbhh, dout, l == N_LAYERS - 1);
    }
}

// round 5
// speedup vs baseline: 1.7107x; 1.3719x over previous
#include <cuda_runtime.h>
#include <cuda_bf16.h>
#include <cstdint>
#include <math.h>

#define N_NODES 25000
#define M_PAD   25088            // 196 * 128
#define N_EDGES 100000
#define H 64
#define K2 4224                  // 4096 (P edge part) + 64 (h for roots) + 64 (Q for be3)
#define N_LAYERS 3

// ---------------- scratch (static device globals) ---------------------------
__device__ float g_h[N_NODES * H];
__device__ float g_hidden[N_NODES * H];
__device__ float g_ew2[N_EDGES * H];
__device__ __align__(128) __nv_bfloat16 g_Phi[(size_t)M_PAD * K2];   // ~212 MB
__device__ __align__(128) __nv_bfloat16 g_Plo[(size_t)M_PAD * K2];   // ~212 MB
__device__ __align__(128) __nv_bfloat16 g_Bhi[H * K2];               // Bt[n][k]
__device__ __align__(128) __nv_bfloat16 g_Blo[H * K2];
__device__ float g_m[N_NODES * H];
__device__ int   g_deg[N_NODES];
__device__ int   g_off[N_NODES + 1];
__device__ int   g_cur[N_NODES];
__device__ int   g_csr[N_EDGES];

// ---------------- helpers ------------------------------------------------
__device__ __forceinline__ uint32_t smem_u32(const void* p) {
    uint32_t a;
    asm("{ .reg .u64 t; cvta.to.shared.u64 t, %1; cvt.u32.u64 %0, t; }" : "=r"(a) : "l"(p));
    return a;
}

__device__ __forceinline__ void mma16816(float* c, const uint32_t* a, uint32_t b0, uint32_t b1) {
    asm volatile("mma.sync.aligned.m16n8k16.row.col.f32.bf16.bf16.f32 "
        "{%0,%1,%2,%3}, {%4,%5,%6,%7}, {%8,%9}, {%0,%1,%2,%3};"
        : "+f"(c[0]), "+f"(c[1]), "+f"(c[2]), "+f"(c[3])
        : "r"(a[0]), "r"(a[1]), "r"(a[2]), "r"(a[3]), "r"(b0), "r"(b1));
}

__device__ __forceinline__ void split_bf(float v, __nv_bfloat16& hi, __nv_bfloat16& lo) {
    hi = __float2bfloat16(v);
    lo = __float2bfloat16(v - __bfloat162float(hi));
}
__device__ __forceinline__ uint32_t pack_bf2(__nv_bfloat16 a, __nv_bfloat16 b) {
    uint16_t ua = *(uint16_t*)&a, ub = *(uint16_t*)&b;
    return (uint32_t)ua | ((uint32_t)ub << 16);
}

// ---------------- zero init --------------------------------------------------
__global__ void k_zero_misc() {
    int i = blockIdx.x * blockDim.x + threadIdx.x;
    int st = gridDim.x * blockDim.x;
    for (int idx = i; idx < N_NODES; idx += st) g_deg[idx] = 0;
    for (int idx = i; idx < N_NODES * H; idx += st) g_hidden[idx] = 0.f;
    const size_t padN = (size_t)(M_PAD - N_NODES) * K2;
    __nv_bfloat16 z = __float2bfloat16(0.f);
    for (size_t idx = i; idx < padN; idx += st) {
        g_Phi[(size_t)N_NODES * K2 + idx] = z;
        g_Plo[(size_t)N_NODES * K2 + idx] = z;
    }
}

// ---------------- node MLP ---------------------------------------------------
__global__ void k_node_mlp(const float* __restrict__ x,
                           const float* __restrict__ W1, const float* __restrict__ b1,
                           const float* __restrict__ W2, const float* __restrict__ b2,
                           const float* __restrict__ W3, const float* __restrict__ b3) {
    __shared__ float W1T[32 * 64], W2T[64 * 64], W3T[64 * 64];
    __shared__ float b1s[64], b2s[64], b3s[64];
    __shared__ float xs[4][32], h1[4][64], h2[4][64];
    int tid = threadIdx.x;
    for (int idx = tid; idx < 32 * 64; idx += 256) { int o = idx / 32, j = idx % 32; W1T[j * 64 + o] = W1[idx]; }
    for (int idx = tid; idx < 64 * 64; idx += 256) { int o = idx / 64, j = idx % 64; W2T[j * 64 + o] = W2[idx]; W3T[j * 64 + o] = W3[idx]; }
    if (tid < 64) { b1s[tid] = b1[tid]; b2s[tid] = b2[tid]; b3s[tid] = b3[tid]; }
    __syncthreads();
    int nl = tid >> 6, o = tid & 63;
    for (int base = blockIdx.x * 4; base < N_NODES; base += gridDim.x * 4) {
        int node = base + nl;
        if (o < 32 && node < N_NODES) xs[nl][o] = x[node * 32 + o];
        __syncthreads();
        if (node < N_NODES) {
            float a = b1s[o];
            #pragma unroll
            for (int j = 0; j < 32; j++) a += xs[nl][j] * W1T[j * 64 + o];
            h1[nl][o] = fmaxf(a, 0.f);
        }
        __syncthreads();
        if (node < N_NODES) {
            float a = b2s[o];
            #pragma unroll
            for (int j = 0; j < 64; j++) a += h1[nl][j] * W2T[j * 64 + o];
            h2[nl][o] = fmaxf(a, 0.f);
        }
        __syncthreads();
        if (node < N_NODES) {
            float a = b3s[o];
            #pragma unroll
            for (int j = 0; j < 64; j++) a += h2[nl][j] * W3T[j * 64 + o];
            g_h[node * 64 + o] = a;
        }
        __syncthreads();
    }
}

// ---------------- edge MLP (layers 1,2) --------------------------------------
__global__ void k_edge_mlp(const float* __restrict__ ea,
                           const float* __restrict__ W1, const float* __restrict__ b1,
                           const float* __restrict__ W2, const float* __restrict__ b2) {
    __shared__ float W1T[16 * 64], W2T[64 * 64];
    __shared__ float b1s[64], b2s[64];
    __shared__ float es[4][16], h1[4][64];
    int tid = threadIdx.x;
    for (int idx = tid; idx < 16 * 64; idx += 256) { int o = idx >> 4, j = idx & 15; W1T[j * 64 + o] = W1[idx]; }
    for (int idx = tid; idx < 64 * 64; idx += 256) { int o = idx >> 6, j = idx & 63; W2T[j * 64 + o] = W2[idx]; }
    if (tid < 64) { b1s[tid] = b1[tid]; b2s[tid] = b2[tid]; }
    __syncthreads();
    int nl = tid >> 6, o = tid & 63;
    for (int base = blockIdx.x * 4; base < N_EDGES; base += gridDim.x * 4) {
        int e = base + nl;
        if (o < 16 && e < N_EDGES) es[nl][o] = ea[e * 16 + o];
        __syncthreads();
        if (e < N_EDGES) {
            float a = b1s[o];
            #pragma unroll
            for (int j = 0; j < 16; j++) a += es[nl][j] * W1T[j * 64 + o];
            h1[nl][o] = fmaxf(a, 0.f);
        }
        __syncthreads();
        if (e < N_EDGES) {
            float a = b2s[o];
            #pragma unroll
            for (int j = 0; j < 64; j++) a += h1[nl][j] * W2T[j * 64 + o];
            g_ew2[e * 64 + o] = fmaxf(a, 0.f);
        }
        __syncthreads();
    }
}

// ---------------- CSR build --------------------------------------------------
__global__ void k_hist(const int* __restrict__ ei) {
    int i = blockIdx.x * blockDim.x + threadIdx.x, st = gridDim.x * blockDim.x;
    for (int e = i; e < N_EDGES; e += st) atomicAdd(&g_deg[ei[N_EDGES + e]], 1);
}

__global__ void k_scan() {
    __shared__ int part[1024];
    int t = threadIdx.x;
    const int CH = (N_NODES + 1023) / 1024;
    int b0 = t * CH, b1 = min(b0 + CH, N_NODES);
    int s = 0;
    for (int i = b0; i < b1; i++) s += g_deg[i];
    part[t] = s;
    __syncthreads();
    for (int d = 1; d < 1024; d <<= 1) {
        int v = (t >= d) ? part[t - d] : 0;
        __syncthreads();
        part[t] += v;
        __syncthreads();
    }
    int run = (t == 0) ? 0 : part[t - 1];
    for (int i = b0; i < b1; i++) { g_off[i] = run; g_cur[i] = run; run += g_deg[i]; }
    if (t == 1023) g_off[N_NODES] = part[1023];
}

__global__ void k_fill(const int* __restrict__ ei) {
    int i = blockIdx.x * blockDim.x + threadIdx.x, st = gridDim.x * blockDim.x;
    for (int e = i; e < N_EDGES; e += st) {
        int d = ei[N_EDGES + e];
        int p = atomicAdd(&g_cur[d], 1);
        g_csr[p] = e;
    }
}

// sort each node's CSR segment ascending (once; makes all layer sums deterministic)
__global__ void k_sort() {
    int d = blockIdx.x * blockDim.x + threadIdx.x;
    if (d >= N_NODES) return;
    int a = g_off[d], b = g_off[d + 1];
    for (int i = a + 1; i < b; i++) {
        int v = g_csr[i];
        int j = i - 1;
        while (j >= a && g_csr[j] > v) { g_csr[j + 1] = g_csr[j]; j--; }
        g_csr[j + 1] = v;
    }
}

// ---------------- build Bt[n][k] (bf16 hi/lo) for layer l --------------------
__global__ void k_buildB(const float* __restrict__ We3, const float* __restrict__ be3,
                         const float* __restrict__ roots, int l) {
    int i0 = blockIdx.x * blockDim.x + threadIdx.x, st = gridDim.x * blockDim.x;
    for (int idx = i0; idx < H * K2; idx += st) {
        int n = idx / K2, kg = idx % K2;
        float v;
        if (kg < 4096)      { int i = kg >> 6, k = kg & 63; v = We3[((i << 6) + n) * 64 + k]; }
        else if (kg < 4160) { v = roots[(l * 64 + (kg - 4096)) * 64 + n]; }
        else                { v = be3[((kg - 4160) << 6) + n]; }
        __nv_bfloat16 hi, lo;
        split_bf(v, hi, lo);
        g_Bhi[idx] = hi;
        g_Blo[idx] = lo;
    }
}

// ---------------- build P rows (register accumulation) ------------------------
// Block = 128 threads = 4 warps = 2 nodes x 2 k-halves. Each warp accumulates
// acc[i] (i=0..63) for k = kh*32 + lane in registers over the node's sorted
// edge list, stages through padded smem, then all threads cooperatively
// convert to bf16 hi/lo and write vectorized.
__global__ void __launch_bounds__(128) k_buildP(const int* __restrict__ ei) {
    __shared__ float stg[2][64][68];          // 68-float stride: 16B-aligned rows
    int tid = threadIdx.x, warp = tid >> 5, lane = tid & 31;
    int ns_w = warp >> 1, kh = warp & 1;
    int d = blockIdx.x * 2 + ns_w;            // 12500 blocks * 2 = 25000 exact
    int kcol = kh * 32 + lane;

    float acc[64];
    #pragma unroll
    for (int i = 0; i < 64; i++) acc[i] = 0.f;

    int off0 = g_off[d];
    int deg = g_off[d + 1] - off0;
    for (int j = 0; j < deg; j++) {
        int e = g_csr[off0 + j];               // sorted -> deterministic order
        int s = ei[e];
        float ew = g_ew2[e * 64 + kcol];
        const float4* hr = (const float4*)(g_h + s * 64);
        #pragma unroll
        for (int i4 = 0; i4 < 16; i4++) {
            float4 hv = hr[i4];                // broadcast load (L1 hit)
            acc[i4 * 4 + 0] += hv.x * ew;
            acc[i4 * 4 + 1] += hv.y * ew;
            acc[i4 * 4 + 2] += hv.z * ew;
            acc[i4 * 4 + 3] += hv.w * ew;
        }
    }
    #pragma unroll
    for (int i = 0; i < 64; i++) stg[ns_w][i][kcol] = acc[i];
    __syncthreads();

    // cooperative writeout of both nodes' 4096-element P slabs
    #pragma unroll 1
    for (int ns = 0; ns < 2; ns++) {
        int dn = blockIdx.x * 2 + ns;
        size_t rb = (size_t)dn * K2;
        uint2* phi = (uint2*)(g_Phi + rb);
        uint2* plo = (uint2*)(g_Plo + rb);
        for (int t4 = tid; t4 < 1024; t4 += 128) {   // 4096 elems / 4
            int i = t4 >> 4, c4 = t4 & 15;
            float4 v = *(const float4*)&stg[ns][i][c4 * 4];
            __nv_bfloat16 h0, l0, h1, l1, h2, l2, h3, l3;
            split_bf(v.x, h0, l0); split_bf(v.y, h1, l1);
            split_bf(v.z, h2, l2); split_bf(v.w, h3, l3);
            uint2 hv2, lv2;
            hv2.x = pack_bf2(h0, h1); hv2.y = pack_bf2(h2, h3);
            lv2.x = pack_bf2(l0, l1); lv2.y = pack_bf2(l2, l3);
            phi[t4] = hv2;
            plo[t4] = lv2;
        }
    }

    // tail: h row (cols 4096..4159) and Q row (4160..4223) for both nodes
    {
        int ns = tid >> 6, i = tid & 63;
        int dn = blockIdx.x * 2 + ns;
        size_t rb = (size_t)dn * K2;
        __nv_bfloat16 hi, lo;
        float hv = g_h[dn * 64 + i];
        split_bf(hv, hi, lo);
        g_Phi[rb + 4096 + i] = hi;
        g_Plo[rb + 4096 + i] = lo;
        int o0 = g_off[dn], dg = g_off[dn + 1] - o0;
        float q = 0.f;
        for (int j = 0; j < dg; j++) q += g_h[ei[g_csr[o0 + j]] * 64 + i];
        split_bf(q, hi, lo);
        g_Phi[rb + 4160 + i] = hi;
        g_Plo[rb + 4160 + i] = lo;
    }
}

// ---------------- mma.sync GEMM: m = P @ Bt^T + cbias -------------------------
// 256 threads / 8 warps, M-tile 128 (16 rows/warp), N=64, K-blocks of 32,
// 3-stage cp.async pipeline. Padded rows of 40 bf16 (80B) -> conflict-free LDS.
#define KBLK 32
#define NKB2 132                 // K2 / 32
#define ST_AHI 0
#define ST_ALO 5120
#define ST_BHI 10240
#define ST_BLO 12800
#define ST_ELEMS 15360           // 30720 bytes
#define GEMM_SMEM (3 * ST_ELEMS * 2)

__device__ __forceinline__ void load_stage32(__nv_bfloat16* st, int m0, int kb, int tid) {
    #pragma unroll
    for (int q = 0; q < 6; q++) {
        int c = q * 256 + tid;                  // 1536 chunks of 16B
        const __nv_bfloat16* src;
        __nv_bfloat16* dst;
        if (c < 1024) {                          // A: 2 planes x 128 rows x 4 chunks
            int half = c >> 9, cc = c & 511;
            int row = cc >> 2, c4 = cc & 3;
            const __nv_bfloat16* g = half ? g_Plo : g_Phi;
            src = g + (size_t)(m0 + row) * K2 + kb * 32 + c4 * 8;
            dst = st + (half ? ST_ALO : ST_AHI) + row * 40 + c4 * 8;
        } else {                                 // B: 2 planes x 64 rows x 4 chunks
            int c2 = c - 1024;
            int half = c2 >> 8, cc = c2 & 255;
            int row = cc >> 2, c4 = cc & 3;
            const __nv_bfloat16* g = half ? g_Blo : g_Bhi;
            src = g + (size_t)row * K2 + kb * 32 + c4 * 8;
            dst = st + (half ? ST_BLO : ST_BHI) + row * 40 + c4 * 8;
        }
        asm volatile("cp.async.cg.shared.global [%0], [%1], 16;" :: "r"(smem_u32(dst)), "l"(src));
    }
    asm volatile("cp.async.commit_group;" ::: "memory");
}

__global__ void __launch_bounds__(256, 2) k_gemm_mma(const float* __restrict__ cbias, int l) {
    extern __shared__ __align__(16) __nv_bfloat16 sm[];
    const int tid = threadIdx.x, w = tid >> 5, lane = tid & 31;
    const int m0 = blockIdx.x * 128;
    const int lq = lane >> 2;          // 0..7
    const int lr = lane & 3;           // 0..3

    float acc[8][4];
    #pragma unroll
    for (int na = 0; na < 8; na++)
        #pragma unroll
        for (int v = 0; v < 4; v++) acc[na][v] = 0.f;

    load_stage32(sm + 0 * ST_ELEMS, m0, 0, tid);
    load_stage32(sm + 1 * ST_ELEMS, m0, 1, tid);
    load_stage32(sm + 2 * ST_ELEMS, m0, 2, tid);

    int slot = 0;
    for (int blk = 0; blk < NKB2; blk++) {
        int rem = NKB2 - 1 - blk;
        if (rem >= 2)      asm volatile("cp.async.wait_group 2;" ::: "memory");
        else if (rem == 1) asm volatile("cp.async.wait_group 1;" ::: "memory");
        else               asm volatile("cp.async.wait_group 0;" ::: "memory");
        __syncthreads();
        __nv_bfloat16* st = sm + slot * ST_ELEMS;
        const __nv_bfloat16* Ahi = st + ST_AHI;
        const __nv_bfloat16* Alo = st + ST_ALO;
        const __nv_bfloat16* Bhi = st + ST_BHI;
        const __nv_bfloat16* Blo = st + ST_BLO;

        #pragma unroll
        for (int s = 0; s < 2; s++) {
            int k0 = s * 16;
            int ra = (w * 16 + lq) * 40 + k0 + lr * 2;
            uint32_t ahi[4], alo[4];
            ahi[0] = *(const uint32_t*)&Ahi[ra];
            ahi[1] = *(const uint32_t*)&Ahi[ra + 320];      // +8 rows
            ahi[2] = *(const uint32_t*)&Ahi[ra + 8];
            ahi[3] = *(const uint32_t*)&Ahi[ra + 328];
            alo[0] = *(const uint32_t*)&Alo[ra];
            alo[1] = *(const uint32_t*)&Alo[ra + 320];
            alo[2] = *(const uint32_t*)&Alo[ra + 8];
            alo[3] = *(const uint32_t*)&Alo[ra + 328];
            #pragma unroll
            for (int na = 0; na < 8; na++) {
                int rn = (na * 8 + lq) * 40 + k0 + lr * 2;
                uint32_t bh0 = *(const uint32_t*)&Bhi[rn];
                uint32_t bh1 = *(const uint32_t*)&Bhi[rn + 8];
                uint32_t bl0 = *(const uint32_t*)&Blo[rn];
                uint32_t bl1 = *(const uint32_t*)&Blo[rn + 8];
                mma16816(acc[na], ahi, bh0, bh1);
                mma16816(acc[na], ahi, bl0, bl1);
                mma16816(acc[na], alo, bh0, bh1);
            }
        }
        __syncthreads();
        if (blk + 3 < NKB2) load_stage32(st, m0, blk + 3, tid);
        slot = (slot == 2) ? 0 : slot + 1;
    }

    // epilogue: rows m0 + w*16 + lq (+8), cols na*8 + lr*2 (+1)
    int r0 = m0 + w * 16 + lq;
    #pragma unroll
    for (int na = 0; na < 8; na++) {
        int c0 = na * 8 + lr * 2;
        float bx = cbias[l * 64 + c0], by = cbias[l * 64 + c0 + 1];
        if (r0 < N_NODES) {
            g_m[r0 * 64 + c0]     = acc[na][0] + bx;
            g_m[r0 * 64 + c0 + 1] = acc[na][1] + by;
        }
        if (r0 + 8 < N_NODES) {
            g_m[(r0 + 8) * 64 + c0]     = acc[na][2] + bx;
            g_m[(r0 + 8) * 64 + c0 + 1] = acc[na][3] + by;
        }
    }
}

// ---------------- GRU step ---------------------------------------------------
#define GRU_SMEM ((24576 + 192 * 2 + 64 * 2 + 192 * 2) * 4)
__global__ void k_gru(const float* __restrict__ Wih, const float* __restrict__ Whh,
                      const float* __restrict__ bih, const float* __restrict__ bhh,
                      float* __restrict__ dout, int last) {
    extern __shared__ float smf[];
    float* WihT = smf;
    float* WhhT = smf + 12288;
    float* bihs = smf + 24576;
    float* bhhs = bihs + 192;
    float* ms   = bhhs + 192;
    float* hs   = ms + 64;
    float* gi   = hs + 64;
    float* gh   = gi + 192;
    int t = threadIdx.x;
    for (int idx = t; idx < 192 * 64; idx += 192) {
        int j = idx / 64, i = idx % 64;
        WihT[i * 192 + j] = Wih[idx];
        WhhT[i * 192 + j] = Whh[idx];
    }
    bihs[t] = bih[t]; bhhs[t] = bhh[t];
    __syncthreads();
    for (int node = blockIdx.x; node < N_NODES; node += gridDim.x) {
        if (t < 64) { ms[t] = g_m[node * 64 + t]; hs[t] = g_hidden[node * 64 + t]; }
        __syncthreads();
        float a = bihs[t], b = bhhs[t];
        #pragma unroll 8
        for (int i = 0; i < 64; i++) {
            a += ms[i] * WihT[i * 192 + t];
            b += hs[i] * WhhT[i * 192 + t];
        }
        gi[t] = a; gh[t] = b;
        __syncthreads();
        if (t < 64) {
            float r = 1.f / (1.f + expf(-(gi[t] + gh[t])));
            float z = 1.f / (1.f + expf(-(gi[64 + t] + gh[64 + t])));
            float n = tanhf(gi[128 + t] + r * gh[128 + t]);
            float nh = (1.f - z) * n + z * hs[t];
            g_hidden[node * 64 + t] = nh;
            g_h[node * 64 + t] = nh;
            if (last) dout[node * 64 + t] = nh;
        }
        __syncthreads();
    }
}

// ---------------- launcher ----------------------------------------------------
extern "C" void kernel_launch(void* const* d_in, const int* in_sizes, int n_in,
                              void* d_out, int out_size) {
    const float* x     = (const float*)d_in[0];
    const float* ea    = (const float*)d_in[1];
    const float* Wn1   = (const float*)d_in[2];
    const float* bn1   = (const float*)d_in[3];
    const float* Wn2   = (const float*)d_in[4];
    const float* bn2   = (const float*)d_in[5];
    const float* Wn3   = (const float*)d_in[6];
    const float* bn3   = (const float*)d_in[7];
    const float* We1   = (const float*)d_in[8];
    const float* be1   = (const float*)d_in[9];
    const float* We2   = (const float*)d_in[10];
    const float* be2   = (const float*)d_in[11];
    const float* We3   = (const float*)d_in[12];
    const float* be3   = (const float*)d_in[13];
    const float* roots = (const float*)d_in[14];
    const float* cbias = (const float*)d_in[15];
    const float* gWih  = (const float*)d_in[16];
    const float* gWhh  = (const float*)d_in[17];
    const float* gbih  = (const float*)d_in[18];
    const float* gbhh  = (const float*)d_in[19];
    const int*   ei    = (const int*)d_in[20];
    float* dout = (float*)d_out;

    cudaFuncSetAttribute(k_gru, cudaFuncAttributeMaxDynamicSharedMemorySize, GRU_SMEM);
    cudaFuncSetAttribute(k_gemm_mma, cudaFuncAttributeMaxDynamicSharedMemorySize, GEMM_SMEM);

    k_zero_misc<<<400, 256>>>();
    k_node_mlp<<<296, 256>>>(x, Wn1, bn1, Wn2, bn2, Wn3, bn3);
    k_edge_mlp<<<296, 256>>>(ea, We1, be1, We2, be2);
    k_hist<<<200, 256>>>(ei);
    k_scan<<<1, 1024>>>();
    k_fill<<<200, 256>>>(ei);
    k_sort<<<(N_NODES + 255) / 256, 256>>>();

    for (int l = 0; l < N_LAYERS; l++) {
        k_buildB<<<264, 256>>>(We3, be3, roots, l);
        k_buildP<<<N_NODES / 2, 128>>>(ei);
        k_gemm_mma<<<M_PAD / 128, 256, GEMM_SMEM>>>(cbias, l);
        k_gru<<<296, 192, GRU_SMEM>>>(gWih, gWhh, gbih, gbhh, dout, l == N_LAYERS - 1);
    }
}